// round 1
// baseline (speedup 1.0000x reference)
#include <cuda_runtime.h>
#include <math.h>

#define BB 32
#define MM 1024
#define NN 1024
#define DD 128
#define TM 64
#define TN 64

// ---------------- scratch (device globals: no allocs allowed) ----------------
__device__ float g_nn[(size_t)BB * MM * DD];          // 16 MB soft-NN output
__device__ float g_sq[2][BB * MM];                    // [0]=|clip|^2 rows, [1]=|sent|^2 rows
__device__ float g_partial[2][BB][MM / TM];           // per-CTA loss partials

// ---------------- helpers ----------------
__device__ __forceinline__ float red_max16(float v) {
#pragma unroll
    for (int o = 8; o > 0; o >>= 1) v = fmaxf(v, __shfl_xor_sync(0xffffffffu, v, o));
    return v;
}
__device__ __forceinline__ float red_sum16(float v) {
#pragma unroll
    for (int o = 8; o > 0; o >>= 1) v += __shfl_xor_sync(0xffffffffu, v, o);
    return v;
}

// ---------------- row squared norms ----------------
__global__ void sq_kernel(const float* __restrict__ clip, const float* __restrict__ sent) {
    int gw = (blockIdx.x * blockDim.x + threadIdx.x) >> 5;
    int lane = threadIdx.x & 31;
    if (gw >= 2 * BB * MM) return;
    int sel = (gw >= BB * MM) ? 1 : 0;
    int row = sel ? (gw - BB * MM) : gw;
    const float* src = sel ? sent : clip;
    float4 v = ((const float4*)(src + (size_t)row * DD))[lane];
    float s = v.x * v.x + v.y * v.y + v.z * v.z + v.w * v.w;
#pragma unroll
    for (int o = 16; o > 0; o >>= 1) s += __shfl_xor_sync(0xffffffffu, s, o);
    if (lane == 0) g_sq[sel][row] = s;
}

// ---------------- fused soft-NN (flash-attention style) ----------------
// smem floats: qT[0,8192) kT[8192,16384) vs[16384,24576) ps[24576,28736)
//              rowbuf[28736,28800) sqtile[28800,28864)
#define ATTN_SMEM_FLOATS 28864
#define IDX_SMEM_FLOATS  (8192 + 8192 + 64 + 16)

// swizzled transposed layout: element (m, d) lives at float index
//   (d*16 + ((m>>2) ^ ((d>>2)&15)))*4 + (m&3)
// -> GEMM loads (fixed d, 4 consecutive m) are conflict-free float4s.

__global__ __launch_bounds__(256, 1)
void attn_kernel(const float* __restrict__ q, const float* __restrict__ kv,
                 int tsel, const float* __restrict__ tlens) {
    extern __shared__ float sm[];
    float* qT = sm;
    float* kT = sm + 8192;
    float* vs = sm + 16384;
    float* ps = sm + 24576;
    float* rowbuf = sm + 28736;
    float* sqtile = sm + 28800;

    const int b = blockIdx.y;
    const int r0 = blockIdx.x * TM;
    const int tid = threadIdx.x;
    const int ty = tid >> 4, tx = tid & 15;     // S-fragment layout (rows 4ty.., cols 4tx..)
    const int mg = tid & 15, dg = tid >> 4;     // PV/acc layout (rows 4mg.., dcols 8dg..)

    // ---- load Q tile, transpose + swizzle into qT ----
    {
        const float4* q4 = (const float4*)(q + ((size_t)b * MM + r0) * DD);
#pragma unroll
        for (int it = 0; it < 8; ++it) {
            int t = tid + it * 256;
            int r = t >> 5, c4 = t & 31;
            float4 val = q4[t];
            int rg = r >> 2, ri = r & 3;
            int gb = rg ^ (c4 & 15);
            int d0 = 4 * c4;
            qT[((d0 + 0) * 16 + gb) * 4 + ri] = val.x;
            qT[((d0 + 1) * 16 + gb) * 4 + ri] = val.y;
            qT[((d0 + 2) * 16 + gb) * 4 + ri] = val.z;
            qT[((d0 + 3) * 16 + gb) * 4 + ri] = val.w;
        }
    }

    float m_i[4], l_i[4], acc[4][8];
#pragma unroll
    for (int r = 0; r < 4; r++) { m_i[r] = -3.0e38f; l_i[r] = 0.f; }
#pragma unroll
    for (int r = 0; r < 4; r++)
#pragma unroll
        for (int c = 0; c < 8; c++) acc[r][c] = 0.f;

    const int len = (int)__ldg(&tlens[b]);
    const int ntiles = (len + TN - 1) / TN;
    const float4* kv4 = (const float4*)(kv + (size_t)b * NN * DD);
    const float* sqrow = &g_sq[tsel][b * NN];
    const float invD = 1.0f / (float)DD;

    for (int t0 = 0; t0 < ntiles; ++t0) {
        const int n0 = t0 * TN;
        __syncthreads();   // prev GEMM2 done with ps/vs/kT/rowbuf
        // ---- load K/V tile: vs row-major + kT transposed/swizzled ----
#pragma unroll
        for (int it = 0; it < 8; ++it) {
            int t = tid + it * 256;
            int r = t >> 5, c4 = t & 31;
            float4 val = kv4[(size_t)n0 * 32 + t];
            ((float4*)vs)[t] = val;
            int rg = r >> 2, ri = r & 3;
            int gb = rg ^ (c4 & 15);
            int d0 = 4 * c4;
            kT[((d0 + 0) * 16 + gb) * 4 + ri] = val.x;
            kT[((d0 + 1) * 16 + gb) * 4 + ri] = val.y;
            kT[((d0 + 2) * 16 + gb) * 4 + ri] = val.z;
            kT[((d0 + 3) * 16 + gb) * 4 + ri] = val.w;
        }
        if (tid < TN) sqtile[tid] = sqrow[n0 + tid];
        __syncthreads();

        // ---- GEMM1: S = Q K^T (4x4 fragment) ----
        float s[4][4];
#pragma unroll
        for (int r = 0; r < 4; r++)
#pragma unroll
            for (int c = 0; c < 4; c++) s[r][c] = 0.f;
        const float4* qT4 = (const float4*)qT;
        const float4* kT4 = (const float4*)kT;
#pragma unroll 4
        for (int d4 = 0; d4 < 32; ++d4) {
            int sw = d4 & 15;
            int qi = ty ^ sw;
            int ki = tx ^ sw;
#pragma unroll
            for (int i2 = 0; i2 < 4; i2++) {
                int d = 4 * d4 + i2;
                float4 a = qT4[d * 16 + qi];
                float4 bb = kT4[d * 16 + ki];
                float av[4] = {a.x, a.y, a.z, a.w};
                float bv[4] = {bb.x, bb.y, bb.z, bb.w};
#pragma unroll
                for (int r = 0; r < 4; r++)
#pragma unroll
                    for (int c = 0; c < 4; c++) s[r][c] = fmaf(av[r], bv[c], s[r][c]);
            }
        }

        // ---- online softmax update ----
#pragma unroll
        for (int r = 0; r < 4; r++) {
            float mx = -3.0e38f;
#pragma unroll
            for (int c = 0; c < 4; c++) {
                int n = n0 + 4 * tx + c;
                float sc = (n < len) ? (2.0f * s[r][c] - sqtile[4 * tx + c]) * invD : -3.0e38f;
                s[r][c] = sc;
                mx = fmaxf(mx, sc);
            }
            mx = red_max16(mx);
            float nm = fmaxf(m_i[r], mx);
            float scale = __expf(m_i[r] - nm);
            float ts = 0.f;
#pragma unroll
            for (int c = 0; c < 4; c++) {
                float p = __expf(s[r][c] - nm);
                s[r][c] = p;
                ts += p;
            }
            ts = red_sum16(ts);
            l_i[r] = l_i[r] * scale + ts;
            m_i[r] = nm;
            if (tx == 0) rowbuf[4 * ty + r] = scale;
        }
        // ---- stage P ----
#pragma unroll
        for (int r = 0; r < 4; r++)
#pragma unroll
            for (int c = 0; c < 4; c++)
                ps[(4 * ty + r) * 65 + 4 * tx + c] = s[r][c];
        __syncthreads();

        // ---- GEMM2: acc = acc*scale + P V ----
        float rsc[4];
#pragma unroll
        for (int r = 0; r < 4; r++) rsc[r] = rowbuf[4 * mg + r];
#pragma unroll
        for (int r = 0; r < 4; r++)
#pragma unroll
            for (int c = 0; c < 8; c++) acc[r][c] *= rsc[r];
#pragma unroll 4
        for (int n = 0; n < TN; ++n) {
            float pv[4];
#pragma unroll
            for (int r = 0; r < 4; r++) pv[r] = ps[(4 * mg + r) * 65 + n];
            float4 v0 = *(const float4*)(vs + n * DD + 8 * dg);
            float4 v1 = *(const float4*)(vs + n * DD + 8 * dg + 4);
            float vv[8] = {v0.x, v0.y, v0.z, v0.w, v1.x, v1.y, v1.z, v1.w};
#pragma unroll
            for (int r = 0; r < 4; r++)
#pragma unroll
                for (int c = 0; c < 8; c++) acc[r][c] = fmaf(pv[r], vv[c], acc[r][c]);
        }
    }

    // ---- epilogue: divide by l, store nn ----
    __syncthreads();
    if (tx == 0) {
#pragma unroll
        for (int r = 0; r < 4; r++) rowbuf[4 * ty + r] = l_i[r];
    }
    __syncthreads();
    float* outp = g_nn + ((size_t)b * MM + r0) * DD;
#pragma unroll
    for (int r = 0; r < 4; r++) {
        float inv = 1.0f / rowbuf[4 * mg + r];
        float4 o0 = make_float4(acc[r][0] * inv, acc[r][1] * inv, acc[r][2] * inv, acc[r][3] * inv);
        float4 o1 = make_float4(acc[r][4] * inv, acc[r][5] * inv, acc[r][6] * inv, acc[r][7] * inv);
        *(float4*)(outp + (4 * mg + r) * DD + 8 * dg) = o0;
        *(float4*)(outp + (4 * mg + r) * DD + 8 * dg + 4) = o1;
    }
}

// ---------------- second soft-NN: only expected index + loss partials ----------------
__global__ __launch_bounds__(256, 1)
void idx_kernel(const float* __restrict__ kemb, int tsel,
                const float* __restrict__ tlens, const float* __restrict__ slens,
                int cyc) {
    extern __shared__ float sm[];
    float* qT = sm;
    float* kT = sm + 8192;
    float* sqtile = sm + 16384;
    float* csum = sm + 16448;

    const int b = blockIdx.y;
    const int r0 = blockIdx.x * TM;
    const int tid = threadIdx.x;
    const int ty = tid >> 4, tx = tid & 15;

    {
        const float4* q4 = (const float4*)(g_nn + ((size_t)b * MM + r0) * DD);
#pragma unroll
        for (int it = 0; it < 8; ++it) {
            int t = tid + it * 256;
            int r = t >> 5, c4 = t & 31;
            float4 val = q4[t];
            int rg = r >> 2, ri = r & 3;
            int gb = rg ^ (c4 & 15);
            int d0 = 4 * c4;
            qT[((d0 + 0) * 16 + gb) * 4 + ri] = val.x;
            qT[((d0 + 1) * 16 + gb) * 4 + ri] = val.y;
            qT[((d0 + 2) * 16 + gb) * 4 + ri] = val.z;
            qT[((d0 + 3) * 16 + gb) * 4 + ri] = val.w;
        }
    }

    float m_i[4], l_i[4], w_i[4];
#pragma unroll
    for (int r = 0; r < 4; r++) { m_i[r] = -3.0e38f; l_i[r] = 0.f; w_i[r] = 0.f; }

    const int len = (int)__ldg(&tlens[b]);
    const int ntiles = (len + TN - 1) / TN;
    const float4* kv4 = (const float4*)(kemb + (size_t)b * NN * DD);
    const float* sqrow = &g_sq[tsel][b * NN];
    const float invD = 1.0f / (float)DD;

    for (int t0 = 0; t0 < ntiles; ++t0) {
        const int n0 = t0 * TN;
        __syncthreads();
#pragma unroll
        for (int it = 0; it < 8; ++it) {
            int t = tid + it * 256;
            int r = t >> 5, c4 = t & 31;
            float4 val = kv4[(size_t)n0 * 32 + t];
            int rg = r >> 2, ri = r & 3;
            int gb = rg ^ (c4 & 15);
            int d0 = 4 * c4;
            kT[((d0 + 0) * 16 + gb) * 4 + ri] = val.x;
            kT[((d0 + 1) * 16 + gb) * 4 + ri] = val.y;
            kT[((d0 + 2) * 16 + gb) * 4 + ri] = val.z;
            kT[((d0 + 3) * 16 + gb) * 4 + ri] = val.w;
        }
        if (tid < TN) sqtile[tid] = sqrow[n0 + tid];
        __syncthreads();

        float s[4][4];
#pragma unroll
        for (int r = 0; r < 4; r++)
#pragma unroll
            for (int c = 0; c < 4; c++) s[r][c] = 0.f;
        const float4* qT4 = (const float4*)qT;
        const float4* kT4 = (const float4*)kT;
#pragma unroll 4
        for (int d4 = 0; d4 < 32; ++d4) {
            int sw = d4 & 15;
            int qi = ty ^ sw;
            int ki = tx ^ sw;
#pragma unroll
            for (int i2 = 0; i2 < 4; i2++) {
                int d = 4 * d4 + i2;
                float4 a = qT4[d * 16 + qi];
                float4 bb = kT4[d * 16 + ki];
                float av[4] = {a.x, a.y, a.z, a.w};
                float bv[4] = {bb.x, bb.y, bb.z, bb.w};
#pragma unroll
                for (int r = 0; r < 4; r++)
#pragma unroll
                    for (int c = 0; c < 4; c++) s[r][c] = fmaf(av[r], bv[c], s[r][c]);
            }
        }

#pragma unroll
        for (int r = 0; r < 4; r++) {
            float mx = -3.0e38f;
#pragma unroll
            for (int c = 0; c < 4; c++) {
                int n = n0 + 4 * tx + c;
                float sc = (n < len) ? (2.0f * s[r][c] - sqtile[4 * tx + c]) * invD : -3.0e38f;
                s[r][c] = sc;
                mx = fmaxf(mx, sc);
            }
            mx = red_max16(mx);
            float nm = fmaxf(m_i[r], mx);
            float scale = __expf(m_i[r] - nm);
            float ts = 0.f, tw = 0.f;
#pragma unroll
            for (int c = 0; c < 4; c++) {
                float p = __expf(s[r][c] - nm);
                ts += p;
                tw += p * (float)(n0 + 4 * tx + c);
            }
            ts = red_sum16(ts);
            tw = red_sum16(tw);
            l_i[r] = l_i[r] * scale + ts;
            w_i[r] = w_i[r] * scale + tw;
            m_i[r] = nm;
        }
    }

    const int slen = (int)__ldg(&slens[b]);
    if (tx == 0) {
        float cs = 0.f;
#pragma unroll
        for (int r = 0; r < 4; r++) {
            int ig = r0 + 4 * ty + r;
            if (ig < slen) {
                float d = w_i[r] / l_i[r] - (float)ig;
                cs += d * d;
            }
        }
        csum[ty] = cs;
    }
    __syncthreads();
    if (tid == 0) {
        float s = 0.f;
        for (int k2 = 0; k2 < 16; k2++) s += csum[k2];
        g_partial[cyc][b][blockIdx.x] = s;
    }
}

// ---------------- deterministic finalize ----------------
__global__ void finalize_kernel(const float* __restrict__ clip_lens,
                                const float* __restrict__ sent_lens,
                                float* __restrict__ out) {
    int b = threadIdx.x;  // 32 threads
#pragma unroll
    for (int cyc = 0; cyc < 2; ++cyc) {
        const float* lens = cyc ? sent_lens : clip_lens;
        float s = 0.f;
        for (int k2 = 0; k2 < MM / TM; k2++) s += g_partial[cyc][b][k2];
        s /= lens[b];
#pragma unroll
        for (int o = 16; o > 0; o >>= 1) s += __shfl_xor_sync(0xffffffffu, s, o);
        if (b == 0) out[cyc] = s / (float)BB;
        __syncwarp();
    }
}

// ---------------- launch ----------------
extern "C" void kernel_launch(void* const* d_in, const int* in_sizes, int n_in,
                              void* d_out, int out_size) {
    const float* clip      = (const float*)d_in[0];
    const float* clip_lens = (const float*)d_in[2];
    const float* sent      = (const float*)d_in[3];
    const float* sent_lens = (const float*)d_in[5];
    float* out = (float*)d_out;

    cudaFuncSetAttribute(attn_kernel, cudaFuncAttributeMaxDynamicSharedMemorySize,
                         ATTN_SMEM_FLOATS * 4);
    cudaFuncSetAttribute(idx_kernel, cudaFuncAttributeMaxDynamicSharedMemorySize,
                         IDX_SMEM_FLOATS * 4);

    sq_kernel<<<(2 * BB * MM * 32) / 256, 256>>>(clip, sent);

    dim3 grid(MM / TM, BB);
    // cycle 1: clip -> sent -> clip
    attn_kernel<<<grid, 256, ATTN_SMEM_FLOATS * 4>>>(clip, sent, 1, sent_lens);
    idx_kernel<<<grid, 256, IDX_SMEM_FLOATS * 4>>>(clip, 0, clip_lens, clip_lens, 0);
    // cycle 2: sent -> clip -> sent
    attn_kernel<<<grid, 256, ATTN_SMEM_FLOATS * 4>>>(sent, clip, 0, clip_lens);
    idx_kernel<<<grid, 256, IDX_SMEM_FLOATS * 4>>>(sent, 1, sent_lens, sent_lens, 1);

    finalize_kernel<<<1, 32>>>(clip_lens, sent_lens, out);
}

// round 2
// speedup vs baseline: 1.2730x; 1.2730x over previous
#include <cuda_runtime.h>

#define BB 32
#define MM 1024
#define NN 1024
#define DD 128
#define TM 128
#define TN 64
#define NT 256

// ---------------- scratch ----------------
__device__ float g_sq[2][BB * MM];              // [0]=clip row norms, [1]=sent
__device__ float g_partial[2][BB][MM / TM];     // per-CTA loss partials

// ---------------- smem layout (floats) ----------------
#define SM_QT 0
#define SM_KT 16384
#define SM_VS 24576
#define SM_PS 32768           /* 128*65 = 8320 */
#define SM_RB 41088           /* 128 */
#define SM_SQ 41216           /* 64 */
#define SM_CS 41280           /* 16 */
#define SMF   41296

// ---------------- helpers ----------------
__device__ __forceinline__ float ex2(float x) {
    float y; asm("ex2.approx.ftz.f32 %0, %1;" : "=f"(y) : "f"(x)); return y;
}
__device__ __forceinline__ float rmax16(float v) {
#pragma unroll
    for (int o = 8; o; o >>= 1) v = fmaxf(v, __shfl_xor_sync(0xffffffffu, v, o));
    return v;
}
__device__ __forceinline__ float rsum16(float v) {
#pragma unroll
    for (int o = 8; o; o >>= 1) v += __shfl_xor_sync(0xffffffffu, v, o);
    return v;
}

// ---------------- row squared norms ----------------
__global__ void sq_kernel(const float* __restrict__ clip, const float* __restrict__ sent) {
    int gw = (blockIdx.x * blockDim.x + threadIdx.x) >> 5;
    int lane = threadIdx.x & 31;
    if (gw >= 2 * BB * MM) return;
    int sel = (gw >= BB * MM) ? 1 : 0;
    int row = sel ? (gw - BB * MM) : gw;
    const float* src = sel ? sent : clip;
    float4 v = ((const float4*)(src + (size_t)row * DD))[lane];
    float s = v.x * v.x + v.y * v.y + v.z * v.z + v.w * v.w;
#pragma unroll
    for (int o = 16; o > 0; o >>= 1) s += __shfl_xor_sync(0xffffffffu, s, o);
    if (lane == 0) g_sq[sel][row] = s;
}

// ---------------- GEMM1: S[128x64] fragment 8x4 per thread ----------------
// qT swizzle (TM=128, 32 granules/d): (m,d) at (d*32 + ((m>>2)^((d>>2)&31)))*4 + (m&3)
// kT swizzle (TN=64,  16 granules/d): (n,d) at (d*16 + ((n>>2)^((d>>2)&15)))*4 + (n&3)
__device__ __forceinline__ void gemm1(const float4* __restrict__ qT4,
                                      const float4* __restrict__ kT4,
                                      int ty, int tx, float s[8][4]) {
#pragma unroll
    for (int r = 0; r < 8; r++)
#pragma unroll
        for (int c = 0; c < 4; c++) s[r][c] = 0.f;
#pragma unroll 2
    for (int d4 = 0; d4 < 32; ++d4) {
        int a0 = (2 * ty) ^ d4;      // granule with rows 8ty..8ty+3
        int a1 = a0 ^ 1;             // granule with rows 8ty+4..8ty+7
        int kg = tx ^ (d4 & 15);
#pragma unroll
        for (int j = 0; j < 4; ++j) {
            int d = 4 * d4 + j;
            float4 qa = qT4[d * 32 + a0];
            float4 qb = qT4[d * 32 + a1];
            float4 kb = kT4[d * 16 + kg];
            float av[8] = {qa.x, qa.y, qa.z, qa.w, qb.x, qb.y, qb.z, qb.w};
            float bv[4] = {kb.x, kb.y, kb.z, kb.w};
#pragma unroll
            for (int r = 0; r < 8; r++)
#pragma unroll
                for (int c = 0; c < 4; c++) s[r][c] = fmaf(av[r], bv[c], s[r][c]);
        }
    }
}

// ---------------- fused cycle kernel: soft-NN + expected-index ----------------
__global__ __launch_bounds__(NT, 1)
void fused_kernel(const float* __restrict__ clip, const float* __restrict__ sent,
                  const float* __restrict__ clip_lens, const float* __restrict__ sent_lens) {
    extern __shared__ float sm[];
    float* qT = sm + SM_QT;
    float* kT = sm + SM_KT;
    float* vs = sm + SM_VS;
    float* ps = sm + SM_PS;
    float* rb = sm + SM_RB;
    float* sq = sm + SM_SQ;
    float* cs = sm + SM_CS;
    const float4* qT4 = (const float4*)qT;
    const float4* kT4 = (const float4*)kT;
    const float4* vs4 = (const float4*)vs;

    const int cyc = blockIdx.z;
    const int b = blockIdx.y;
    const int r0 = blockIdx.x * TM;
    const float* qemb  = cyc ? sent : clip;
    const float* kvemb = cyc ? clip : sent;
    const int qsel = cyc, kvsel = cyc ^ 1;
    const int qlen  = (int)(cyc ? sent_lens[b] : clip_lens[b]);
    const int kvlen = (int)(cyc ? clip_lens[b] : sent_lens[b]);

    const int tid = threadIdx.x;
    const int tx = tid & 15, ty = tid >> 4;   // S-frag: rows 8ty.., cols 4tx..
    const int dg = tid & 7, mg = tid >> 3;    // acc: rows 4mg.., dcols {32c+4dg+j}

    const float C2 = 1.4426950408889634f / 128.0f;   // log2(e)/D
    const float C1 = 2.0f * C2;

    // ---- load Q tile (transposed + swizzled) ----
    {
        const float4* q4 = (const float4*)(qemb + ((size_t)b * MM + r0) * DD);
#pragma unroll
        for (int it = 0; it < 16; ++it) {
            int t = tid + it * NT;
            int r = t >> 5, c4 = t & 31, ri = r & 3;
            float4 v = q4[t];
            int gb = (r >> 2) ^ c4;
            qT[((4 * c4 + 0) * 32 + gb) * 4 + ri] = v.x;
            qT[((4 * c4 + 1) * 32 + gb) * 4 + ri] = v.y;
            qT[((4 * c4 + 2) * 32 + gb) * 4 + ri] = v.z;
            qT[((4 * c4 + 3) * 32 + gb) * 4 + ri] = v.w;
        }
    }

    // ================= phase 1: soft-NN  (q vs kv) =================
    float m_i[8], l_i[8];
#pragma unroll
    for (int r = 0; r < 8; r++) { m_i[r] = -1e30f; l_i[r] = 0.f; }
    float acc[4][16];
#pragma unroll
    for (int r = 0; r < 4; r++)
#pragma unroll
        for (int c = 0; c < 16; c++) acc[r][c] = 0.f;

    const float4* kv4 = (const float4*)(kvemb + (size_t)b * NN * DD);
    const float* sqg = &g_sq[kvsel][b * NN];
    const int ntiles = (kvlen + TN - 1) / TN;

    float4 pf[8];
#pragma unroll
    for (int it = 0; it < 8; ++it) pf[it] = kv4[tid + it * NT];

    for (int t0 = 0; t0 < ntiles; ++t0) {
        const int n0 = t0 * TN;
        __syncthreads();   // prev GEMM2 done with kT/vs/ps/rb
        // ---- store prefetched tile: vs row-major + kT transposed ----
#pragma unroll
        for (int it = 0; it < 8; ++it) {
            int t = tid + it * NT;
            int r = t >> 5, c4 = t & 31, ri = r & 3;
            float4 v = pf[it];
            ((float4*)vs)[t] = v;
            int gb = (r >> 2) ^ (c4 & 15);
            kT[((4 * c4 + 0) * 16 + gb) * 4 + ri] = v.x;
            kT[((4 * c4 + 1) * 16 + gb) * 4 + ri] = v.y;
            kT[((4 * c4 + 2) * 16 + gb) * 4 + ri] = v.z;
            kT[((4 * c4 + 3) * 16 + gb) * 4 + ri] = v.w;
        }
        if (tid < TN) sq[tid] = sqg[n0 + tid] * C2;
        __syncthreads();
        if (t0 + 1 < ntiles) {   // prefetch next tile during compute
#pragma unroll
            for (int it = 0; it < 8; ++it)
                pf[it] = kv4[(size_t)(n0 + TN) * 32 + tid + it * NT];
        }

        float s[8][4];
        gemm1(qT4, kT4, ty, tx, s);

        // ---- online softmax (base-2 domain) ----
#pragma unroll
        for (int r = 0; r < 8; r++) {
            float mx = -1e30f;
#pragma unroll
            for (int c = 0; c < 4; c++) {
                int n = n0 + 4 * tx + c;
                float sc = (n < kvlen) ? fmaf(s[r][c], C1, -sq[4 * tx + c]) : -1e30f;
                s[r][c] = sc;
                mx = fmaxf(mx, sc);
            }
            mx = rmax16(mx);
            float nm = fmaxf(m_i[r], mx);
            float scl = ex2(m_i[r] - nm);
            float ts = 0.f;
#pragma unroll
            for (int c = 0; c < 4; c++) { float p = ex2(s[r][c] - nm); s[r][c] = p; ts += p; }
            ts = rsum16(ts);
            l_i[r] = l_i[r] * scl + ts;
            m_i[r] = nm;
            if (tx == 0) rb[8 * ty + r] = scl;
#pragma unroll
            for (int c = 0; c < 4; c++) ps[(8 * ty + r) * 65 + 4 * tx + c] = s[r][c];
        }
        __syncthreads();

        // ---- GEMM2: acc = acc*scale + P V ----
        float rsc[4];
#pragma unroll
        for (int rr = 0; rr < 4; rr++) rsc[rr] = rb[4 * mg + rr];
#pragma unroll
        for (int rr = 0; rr < 4; rr++)
#pragma unroll
            for (int c = 0; c < 16; c++) acc[rr][c] *= rsc[rr];
#pragma unroll 4
        for (int n = 0; n < TN; ++n) {
            float pr[4];
#pragma unroll
            for (int rr = 0; rr < 4; rr++) pr[rr] = ps[(4 * mg + rr) * 65 + n];
#pragma unroll
            for (int c = 0; c < 4; c++) {
                float4 v = vs4[n * 32 + 8 * c + dg];     // d cols 32c+4dg..+3
                float vv[4] = {v.x, v.y, v.z, v.w};
#pragma unroll
                for (int rr = 0; rr < 4; rr++)
#pragma unroll
                    for (int j = 0; j < 4; j++)
                        acc[rr][4 * c + j] = fmaf(pr[rr], vv[j], acc[rr][4 * c + j]);
            }
        }
    }

    // ---- phase-1 epilogue: nn = acc/l, write into qT (swizzled) ----
    __syncthreads();
    if (tx == 0) {
#pragma unroll
        for (int r = 0; r < 8; r++) rb[8 * ty + r] = l_i[r];
    }
    __syncthreads();
#pragma unroll
    for (int rr = 0; rr < 4; ++rr) {
        float inv = 1.0f / rb[4 * mg + rr];
#pragma unroll
        for (int c = 0; c < 4; c++) {
            int gb = mg ^ (8 * c + dg);          // (m>>2)=mg, (d>>2)=8c+dg
#pragma unroll
            for (int j = 0; j < 4; j++) {
                int d = 32 * c + 4 * dg + j;
                qT[(d * 32 + gb) * 4 + rr] = acc[rr][4 * c + j] * inv;
            }
        }
    }

    // ================= phase 2: expected index  (nn vs q-embedding) =================
    float m2[8], l2[8], w2[8];
#pragma unroll
    for (int r = 0; r < 8; r++) { m2[r] = -1e30f; l2[r] = 0.f; w2[r] = 0.f; }

    const float4* kv24 = (const float4*)(qemb + (size_t)b * MM * DD);
    const float* sqg2 = &g_sq[qsel][b * MM];
    const int ntiles2 = (qlen + TN - 1) / TN;
#pragma unroll
    for (int it = 0; it < 8; ++it) pf[it] = kv24[tid + it * NT];

    for (int t0 = 0; t0 < ntiles2; ++t0) {
        const int n0 = t0 * TN;
        __syncthreads();   // covers qT epilogue writes (first iter) + prev GEMM1 kT reads
#pragma unroll
        for (int it = 0; it < 8; ++it) {
            int t = tid + it * NT;
            int r = t >> 5, c4 = t & 31, ri = r & 3;
            float4 v = pf[it];
            int gb = (r >> 2) ^ (c4 & 15);
            kT[((4 * c4 + 0) * 16 + gb) * 4 + ri] = v.x;
            kT[((4 * c4 + 1) * 16 + gb) * 4 + ri] = v.y;
            kT[((4 * c4 + 2) * 16 + gb) * 4 + ri] = v.z;
            kT[((4 * c4 + 3) * 16 + gb) * 4 + ri] = v.w;
        }
        if (tid < TN) sq[tid] = sqg2[n0 + tid] * C2;
        __syncthreads();
        if (t0 + 1 < ntiles2) {
#pragma unroll
            for (int it = 0; it < 8; ++it)
                pf[it] = kv24[(size_t)(n0 + TN) * 32 + tid + it * NT];
        }

        float s[8][4];
        gemm1(qT4, kT4, ty, tx, s);

#pragma unroll
        for (int r = 0; r < 8; r++) {
            float mx = -1e30f;
#pragma unroll
            for (int c = 0; c < 4; c++) {
                int n = n0 + 4 * tx + c;
                float sc = (n < qlen) ? fmaf(s[r][c], C1, -sq[4 * tx + c]) : -1e30f;
                s[r][c] = sc;
                mx = fmaxf(mx, sc);
            }
            mx = rmax16(mx);
            float nm = fmaxf(m2[r], mx);
            float scl = ex2(m2[r] - nm);
            float ts = 0.f, tw = 0.f;
#pragma unroll
            for (int c = 0; c < 4; c++) {
                float p = ex2(s[r][c] - nm);
                ts += p;
                tw = fmaf(p, (float)(n0 + 4 * tx + c), tw);
            }
            ts = rsum16(ts);
            tw = rsum16(tw);
            l2[r] = l2[r] * scl + ts;
            w2[r] = w2[r] * scl + tw;
            m2[r] = nm;
        }
    }

    // ---- loss partial ----
    if (tx == 0) {
        float c = 0.f;
#pragma unroll
        for (int r = 0; r < 8; r++) {
            int ig = r0 + 8 * ty + r;
            if (ig < qlen) {
                float d = w2[r] / l2[r] - (float)ig;
                c = fmaf(d, d, c);
            }
        }
        cs[ty] = c;
    }
    __syncthreads();
    if (tid == 0) {
        float ssum = 0.f;
        for (int k = 0; k < 16; k++) ssum += cs[k];
        g_partial[cyc][b][blockIdx.x] = ssum;
    }
}

// ---------------- deterministic finalize ----------------
__global__ void finalize_kernel(const float* __restrict__ clip_lens,
                                const float* __restrict__ sent_lens,
                                float* __restrict__ out) {
    int b = threadIdx.x;  // 32 threads
#pragma unroll
    for (int cyc = 0; cyc < 2; ++cyc) {
        float s = 0.f;
        for (int k = 0; k < MM / TM; k++) s += g_partial[cyc][b][k];
        s /= (cyc ? sent_lens[b] : clip_lens[b]);
#pragma unroll
        for (int o = 16; o > 0; o >>= 1) s += __shfl_xor_sync(0xffffffffu, s, o);
        if (b == 0) out[cyc] = s / (float)BB;
        __syncwarp();
    }
}

// ---------------- launch ----------------
extern "C" void kernel_launch(void* const* d_in, const int* in_sizes, int n_in,
                              void* d_out, int out_size) {
    const float* clip      = (const float*)d_in[0];
    const float* clip_lens = (const float*)d_in[2];
    const float* sent      = (const float*)d_in[3];
    const float* sent_lens = (const float*)d_in[5];
    float* out = (float*)d_out;

    cudaFuncSetAttribute(fused_kernel, cudaFuncAttributeMaxDynamicSharedMemorySize,
                         SMF * 4);

    sq_kernel<<<(2 * BB * MM * 32) / 256, 256>>>(clip, sent);

    dim3 grid(MM / TM, BB, 2);
    fused_kernel<<<grid, NT, SMF * 4>>>(clip, sent, clip_lens, sent_lens);

    finalize_kernel<<<1, 32>>>(clip_lens, sent_lens, out);
}

// round 3
// speedup vs baseline: 1.4060x; 1.1045x over previous
#include <cuda_runtime.h>

#define BB 32
#define MM 1024
#define NN 1024
#define DD 128
#define TM 128
#define TN 64
#define NT 256

typedef unsigned long long u64;

// ---------------- scratch ----------------
__device__ float g_sq[2][BB * MM];              // [0]=clip row norms, [1]=sent
__device__ float g_partial[2][BB][MM / TM];     // per-CTA loss partials

// ---------------- smem layout (floats) ----------------
#define SM_QT 0
#define SM_KT 16384
#define SM_VS 24576
#define SM_PS 32768           /* 128*65 = 8320 */
#define SM_RB 41088           /* 128 */
#define SM_SQ 41216           /* 64 */
#define SM_CS 41280           /* 16 */
#define SMF   41296

// ---------------- f32x2 helpers ----------------
__device__ __forceinline__ u64 pack2(float lo, float hi) {
    u64 r; asm("mov.b64 %0, {%1, %2};" : "=l"(r) : "f"(lo), "f"(hi)); return r;
}
__device__ __forceinline__ u64 dup2(float v) {
    u64 r; asm("mov.b64 %0, {%1, %1};" : "=l"(r) : "f"(v)); return r;
}
__device__ __forceinline__ void unpack2(u64 p, float& lo, float& hi) {
    asm("mov.b64 {%0, %1}, %2;" : "=f"(lo), "=f"(hi) : "l"(p));
}
__device__ __forceinline__ u64 fma2(u64 a, u64 b, u64 c) {
    u64 d; asm("fma.rn.f32x2 %0, %1, %2, %3;" : "=l"(d) : "l"(a), "l"(b), "l"(c)); return d;
}
__device__ __forceinline__ u64 mul2(u64 a, u64 b) {
    u64 d; asm("mul.rn.f32x2 %0, %1, %2;" : "=l"(d) : "l"(a), "l"(b)); return d;
}

// ---------------- misc helpers ----------------
__device__ __forceinline__ float ex2(float x) {
    float y; asm("ex2.approx.ftz.f32 %0, %1;" : "=f"(y) : "f"(x)); return y;
}
__device__ __forceinline__ float rmax16(float v) {
#pragma unroll
    for (int o = 8; o; o >>= 1) v = fmaxf(v, __shfl_xor_sync(0xffffffffu, v, o));
    return v;
}
__device__ __forceinline__ float rsum16(float v) {
#pragma unroll
    for (int o = 8; o; o >>= 1) v += __shfl_xor_sync(0xffffffffu, v, o);
    return v;
}

// ---------------- row squared norms ----------------
__global__ void sq_kernel(const float* __restrict__ clip, const float* __restrict__ sent) {
    int gw = (blockIdx.x * blockDim.x + threadIdx.x) >> 5;
    int lane = threadIdx.x & 31;
    if (gw >= 2 * BB * MM) return;
    int sel = (gw >= BB * MM) ? 1 : 0;
    int row = sel ? (gw - BB * MM) : gw;
    const float* src = sel ? sent : clip;
    float4 v = ((const float4*)(src + (size_t)row * DD))[lane];
    float s = v.x * v.x + v.y * v.y + v.z * v.z + v.w * v.w;
#pragma unroll
    for (int o = 16; o > 0; o >>= 1) s += __shfl_xor_sync(0xffffffffu, s, o);
    if (lane == 0) g_sq[sel][row] = s;
}

// ---------------- GEMM1: S[128x64], 8x4 fragment, f32x2 packed over rows ----------------
// qT swizzle (32 granules/d): (m,d) at (d*32 + ((m>>2)^((d>>2)&31)))*4 + (m&3)
// kT swizzle (16 granules/d): (n,d) at (d*16 + ((n>>2)^((d>>2)&15)))*4 + (n&3)
__device__ __forceinline__ void gemm1(const float4* __restrict__ qT4,
                                      const float4* __restrict__ kT4,
                                      int ty, int tx, u64 s2[4][4]) {
#pragma unroll
    for (int rp = 0; rp < 4; rp++)
#pragma unroll
        for (int c = 0; c < 4; c++) s2[rp][c] = 0ull;
#pragma unroll 2
    for (int d4 = 0; d4 < 32; ++d4) {
        int a0 = (2 * ty) ^ d4;      // granule with rows 8ty..8ty+3
        int a1 = a0 ^ 1;             // granule with rows 8ty+4..8ty+7
        int kg = tx ^ (d4 & 15);
#pragma unroll
        for (int j = 0; j < 4; ++j) {
            int d = 4 * d4 + j;
            float4 qa = qT4[d * 32 + a0];
            float4 qb = qT4[d * 32 + a1];
            float4 kb = kT4[d * 16 + kg];
            u64 ap[4] = {pack2(qa.x, qa.y), pack2(qa.z, qa.w),
                         pack2(qb.x, qb.y), pack2(qb.z, qb.w)};
            u64 bp[4] = {dup2(kb.x), dup2(kb.y), dup2(kb.z), dup2(kb.w)};
#pragma unroll
            for (int rp = 0; rp < 4; rp++)
#pragma unroll
                for (int c = 0; c < 4; c++) s2[rp][c] = fma2(ap[rp], bp[c], s2[rp][c]);
        }
    }
}

// ---------------- fused cycle kernel: soft-NN + expected-index ----------------
__global__ __launch_bounds__(NT, 1)
void fused_kernel(const float* __restrict__ clip, const float* __restrict__ sent,
                  const float* __restrict__ clip_lens, const float* __restrict__ sent_lens) {
    extern __shared__ float sm[];
    float* qT = sm + SM_QT;
    float* kT = sm + SM_KT;
    float* vs = sm + SM_VS;
    float* ps = sm + SM_PS;
    float* rb = sm + SM_RB;
    float* sq = sm + SM_SQ;
    float* cs = sm + SM_CS;
    const float4* qT4 = (const float4*)qT;
    const float4* kT4 = (const float4*)kT;
    const float4* vs4 = (const float4*)vs;

    const int cyc = blockIdx.z;
    const int b = blockIdx.y;
    const int r0 = blockIdx.x * TM;
    const float* qemb  = cyc ? sent : clip;
    const float* kvemb = cyc ? clip : sent;
    const int qsel = cyc, kvsel = cyc ^ 1;
    const int qlen  = (int)(cyc ? sent_lens[b] : clip_lens[b]);
    const int kvlen = (int)(cyc ? clip_lens[b] : sent_lens[b]);

    const int tid = threadIdx.x;
    const int tx = tid & 15, ty = tid >> 4;   // S-frag: rows 8ty.., cols 4tx..
    const int dg = tid & 7, mg = tid >> 3;    // acc: rows 4mg.., dcols {32c+4dg+j}

    const float C2 = 1.4426950408889634f / 128.0f;   // log2(e)/D
    const float C1 = 2.0f * C2;

    // ---- load Q tile (transposed + swizzled) ----
    {
        const float4* q4 = (const float4*)(qemb + ((size_t)b * MM + r0) * DD);
#pragma unroll
        for (int it = 0; it < 16; ++it) {
            int t = tid + it * NT;
            int r = t >> 5, c4 = t & 31, ri = r & 3;
            float4 v = q4[t];
            int gb = (r >> 2) ^ c4;
            qT[((4 * c4 + 0) * 32 + gb) * 4 + ri] = v.x;
            qT[((4 * c4 + 1) * 32 + gb) * 4 + ri] = v.y;
            qT[((4 * c4 + 2) * 32 + gb) * 4 + ri] = v.z;
            qT[((4 * c4 + 3) * 32 + gb) * 4 + ri] = v.w;
        }
    }

    // ================= phase 1: soft-NN  (q vs kv) =================
    float m_i[8], l_i[8];
#pragma unroll
    for (int r = 0; r < 8; r++) { m_i[r] = -1e30f; l_i[r] = 0.f; }
    u64 acc2[4][8];                           // rows 4mg+rr, packed d pairs
#pragma unroll
    for (int r = 0; r < 4; r++)
#pragma unroll
        for (int c = 0; c < 8; c++) acc2[r][c] = 0ull;

    const float4* kv4 = (const float4*)(kvemb + (size_t)b * NN * DD);
    const float* sqg = &g_sq[kvsel][b * NN];
    const int ntiles = (kvlen + TN - 1) / TN;

    float4 pf[8];
#pragma unroll
    for (int it = 0; it < 8; ++it) pf[it] = kv4[tid + it * NT];

    for (int t0 = 0; t0 < ntiles; ++t0) {
        const int n0 = t0 * TN;
        __syncthreads();   // prev GEMM2 done with kT/vs/ps/rb
#pragma unroll
        for (int it = 0; it < 8; ++it) {
            int t = tid + it * NT;
            int r = t >> 5, c4 = t & 31, ri = r & 3;
            float4 v = pf[it];
            ((float4*)vs)[t] = v;
            int gb = (r >> 2) ^ (c4 & 15);
            kT[((4 * c4 + 0) * 16 + gb) * 4 + ri] = v.x;
            kT[((4 * c4 + 1) * 16 + gb) * 4 + ri] = v.y;
            kT[((4 * c4 + 2) * 16 + gb) * 4 + ri] = v.z;
            kT[((4 * c4 + 3) * 16 + gb) * 4 + ri] = v.w;
        }
        if (tid < TN) sq[tid] = sqg[n0 + tid] * C2;
        __syncthreads();
        if (t0 + 1 < ntiles) {   // prefetch next tile during compute
#pragma unroll
            for (int it = 0; it < 8; ++it)
                pf[it] = kv4[(size_t)(n0 + TN) * 32 + tid + it * NT];
        }

        u64 s2[4][4];
        gemm1(qT4, kT4, ty, tx, s2);
        float s[8][4];
#pragma unroll
        for (int rp = 0; rp < 4; rp++)
#pragma unroll
            for (int c = 0; c < 4; c++) unpack2(s2[rp][c], s[2 * rp][c], s[2 * rp + 1][c]);

        // ---- online softmax (base-2 domain) ----
#pragma unroll
        for (int r = 0; r < 8; r++) {
            float mx = -1e30f;
#pragma unroll
            for (int c = 0; c < 4; c++) {
                int n = n0 + 4 * tx + c;
                float sc = (n < kvlen) ? fmaf(s[r][c], C1, -sq[4 * tx + c]) : -1e30f;
                s[r][c] = sc;
                mx = fmaxf(mx, sc);
            }
            mx = rmax16(mx);
            float nm = fmaxf(m_i[r], mx);
            float scl = ex2(m_i[r] - nm);
            float ts = 0.f;
#pragma unroll
            for (int c = 0; c < 4; c++) { float p = ex2(s[r][c] - nm); s[r][c] = p; ts += p; }
            ts = rsum16(ts);
            l_i[r] = l_i[r] * scl + ts;
            m_i[r] = nm;
            if (tx == 0) rb[8 * ty + r] = scl;
#pragma unroll
            for (int c = 0; c < 4; c++) ps[(8 * ty + r) * 65 + 4 * tx + c] = s[r][c];
        }
        __syncthreads();

        // ---- GEMM2: acc = acc*scale + P V  (f32x2 over d pairs) ----
#pragma unroll
        for (int rr = 0; rr < 4; rr++) {
            u64 rs = dup2(rb[4 * mg + rr]);
#pragma unroll
            for (int c = 0; c < 8; c++) acc2[rr][c] = mul2(acc2[rr][c], rs);
        }
#pragma unroll 4
        for (int n = 0; n < TN; ++n) {
            u64 prd[4];
#pragma unroll
            for (int rr = 0; rr < 4; rr++) prd[rr] = dup2(ps[(4 * mg + rr) * 65 + n]);
#pragma unroll
            for (int c = 0; c < 4; c++) {
                float4 v = vs4[n * 32 + 8 * c + dg];     // d cols 32c+4dg..+3
                u64 v01 = pack2(v.x, v.y);
                u64 v23 = pack2(v.z, v.w);
#pragma unroll
                for (int rr = 0; rr < 4; rr++) {
                    acc2[rr][2 * c + 0] = fma2(prd[rr], v01, acc2[rr][2 * c + 0]);
                    acc2[rr][2 * c + 1] = fma2(prd[rr], v23, acc2[rr][2 * c + 1]);
                }
            }
        }
    }

    // ---- phase-1 epilogue: nn = acc/l, write into qT (swizzled) ----
    __syncthreads();
    if (tx == 0) {
#pragma unroll
        for (int r = 0; r < 8; r++) rb[8 * ty + r] = l_i[r];
    }
    __syncthreads();
#pragma unroll
    for (int rr = 0; rr < 4; ++rr) {
        float inv = 1.0f / rb[4 * mg + rr];
#pragma unroll
        for (int c = 0; c < 4; c++) {
            int gb = mg ^ (8 * c + dg);          // (m>>2)=mg, (d>>2)=8c+dg
#pragma unroll
            for (int jh = 0; jh < 2; jh++) {
                float f0, f1;
                unpack2(acc2[rr][2 * c + jh], f0, f1);
                int d = 32 * c + 4 * dg + 2 * jh;
                qT[(d * 32 + gb) * 4 + rr] = f0 * inv;
                qT[((d + 1) * 32 + gb) * 4 + rr] = f1 * inv;
            }
        }
    }

    // ================= phase 2: expected index  (nn vs q-embedding) =================
    float m2[8], l2[8], w2[8];
#pragma unroll
    for (int r = 0; r < 8; r++) { m2[r] = -1e30f; l2[r] = 0.f; w2[r] = 0.f; }

    const float4* kv24 = (const float4*)(qemb + (size_t)b * MM * DD);
    const float* sqg2 = &g_sq[qsel][b * MM];
    const int ntiles2 = (qlen + TN - 1) / TN;
#pragma unroll
    for (int it = 0; it < 8; ++it) pf[it] = kv24[tid + it * NT];

    for (int t0 = 0; t0 < ntiles2; ++t0) {
        const int n0 = t0 * TN;
        __syncthreads();   // covers qT epilogue writes (first iter) + prev GEMM1 kT reads
#pragma unroll
        for (int it = 0; it < 8; ++it) {
            int t = tid + it * NT;
            int r = t >> 5, c4 = t & 31, ri = r & 3;
            float4 v = pf[it];
            int gb = (r >> 2) ^ (c4 & 15);
            kT[((4 * c4 + 0) * 16 + gb) * 4 + ri] = v.x;
            kT[((4 * c4 + 1) * 16 + gb) * 4 + ri] = v.y;
            kT[((4 * c4 + 2) * 16 + gb) * 4 + ri] = v.z;
            kT[((4 * c4 + 3) * 16 + gb) * 4 + ri] = v.w;
        }
        if (tid < TN) sq[tid] = sqg2[n0 + tid] * C2;
        __syncthreads();
        if (t0 + 1 < ntiles2) {
#pragma unroll
            for (int it = 0; it < 8; ++it)
                pf[it] = kv24[(size_t)(n0 + TN) * 32 + tid + it * NT];
        }

        u64 s2[4][4];
        gemm1(qT4, kT4, ty, tx, s2);
        float s[8][4];
#pragma unroll
        for (int rp = 0; rp < 4; rp++)
#pragma unroll
            for (int c = 0; c < 4; c++) unpack2(s2[rp][c], s[2 * rp][c], s[2 * rp + 1][c]);

#pragma unroll
        for (int r = 0; r < 8; r++) {
            float mx = -1e30f;
#pragma unroll
            for (int c = 0; c < 4; c++) {
                int n = n0 + 4 * tx + c;
                float sc = (n < qlen) ? fmaf(s[r][c], C1, -sq[4 * tx + c]) : -1e30f;
                s[r][c] = sc;
                mx = fmaxf(mx, sc);
            }
            mx = rmax16(mx);
            float nm = fmaxf(m2[r], mx);
            float scl = ex2(m2[r] - nm);
            float ts = 0.f, tw = 0.f;
#pragma unroll
            for (int c = 0; c < 4; c++) {
                float p = ex2(s[r][c] - nm);
                ts += p;
                tw = fmaf(p, (float)(n0 + 4 * tx + c), tw);
            }
            ts = rsum16(ts);
            tw = rsum16(tw);
            l2[r] = l2[r] * scl + ts;
            w2[r] = w2[r] * scl + tw;
            m2[r] = nm;
        }
    }

    // ---- loss partial ----
    if (tx == 0) {
        float c = 0.f;
#pragma unroll
        for (int r = 0; r < 8; r++) {
            int ig = r0 + 8 * ty + r;
            if (ig < qlen) {
                float d = w2[r] / l2[r] - (float)ig;
                c = fmaf(d, d, c);
            }
        }
        cs[ty] = c;
    }
    __syncthreads();
    if (tid == 0) {
        float ssum = 0.f;
        for (int k = 0; k < 16; k++) ssum += cs[k];
        g_partial[cyc][b][blockIdx.x] = ssum;
    }
}

// ---------------- deterministic finalize ----------------
__global__ void finalize_kernel(const float* __restrict__ clip_lens,
                                const float* __restrict__ sent_lens,
                                float* __restrict__ out) {
    int b = threadIdx.x;  // 32 threads
#pragma unroll
    for (int cyc = 0; cyc < 2; ++cyc) {
        float s = 0.f;
        for (int k = 0; k < MM / TM; k++) s += g_partial[cyc][b][k];
        s /= (cyc ? sent_lens[b] : clip_lens[b]);
#pragma unroll
        for (int o = 16; o > 0; o >>= 1) s += __shfl_xor_sync(0xffffffffu, s, o);
        if (b == 0) out[cyc] = s / (float)BB;
        __syncwarp();
    }
}

// ---------------- launch ----------------
extern "C" void kernel_launch(void* const* d_in, const int* in_sizes, int n_in,
                              void* d_out, int out_size) {
    const float* clip      = (const float*)d_in[0];
    const float* clip_lens = (const float*)d_in[2];
    const float* sent      = (const float*)d_in[3];
    const float* sent_lens = (const float*)d_in[5];
    float* out = (float*)d_out;

    cudaFuncSetAttribute(fused_kernel, cudaFuncAttributeMaxDynamicSharedMemorySize,
                         SMF * 4);

    sq_kernel<<<(2 * BB * MM * 32) / 256, 256>>>(clip, sent);

    dim3 grid(MM / TM, BB, 2);
    fused_kernel<<<grid, NT, SMF * 4>>>(clip, sent, clip_lens, sent_lens);

    finalize_kernel<<<1, 32>>>(clip_lens, sent_lens, out);
}